// round 8
// baseline (speedup 1.0000x reference)
#include <cuda_runtime.h>

// ---------------------------------------------------------------------------
// Problem constants
// ---------------------------------------------------------------------------
#define H    156
#define HP   164           // padded row: 164 % 32 == 4 -> conflict-free LDS.128
#define BSZ  4096
#define TT   128
#define NB   32            // samples per block
#define TPB  256
#define NBHP (NB * HP)     // 5248 floats
#define OUT_O 12

#define OUT_SZ  ((size_t)BSZ * H * OUT_O)        // 7,667,712
#define OFF_H   (OUT_SZ)
#define OFF_C   (OFF_H + 2ULL * BSZ * H)

// scratch for layer-1 ht time series: [B][T][H]  (t*156+h flat per sample)
__device__ float g_ys[(size_t)BSZ * TT * H];

__device__ __forceinline__ float sigm(float x) {
    return __fdividef(1.0f, 1.0f + __expf(-x));
}

// ---------------------------------------------------------------------------
// Kernel 1: persistent LSTM+GCN recurrence. 128 blocks x 256 threads.
// SMEM layout (floats):
//   sX  [NBHP]        x_t transposed [n][HP]
//   sC  [2*NBHP]      cell state per layer, [n][HP]
//   sH  [2*2*NBHP]    hidden state per layer, ping-pong by t-parity
//   tC  [NBHP]        GCN relu intermediate (c)
//   tH  [NBHP]        GCN relu intermediate (h)
// total = 9*NBHP floats = 188,928 bytes
// ---------------------------------------------------------------------------
__global__ void __launch_bounds__(TPB, 1) lstm_gcn_kernel(
    const float* __restrict__ x,   const float* __restrict__ adj,
    const float* __restrict__ Wix, const float* __restrict__ bix,
    const float* __restrict__ Wih, const float* __restrict__ bih,
    const float* __restrict__ Wfx, const float* __restrict__ bfx,
    const float* __restrict__ Wfh, const float* __restrict__ bfh,
    const float* __restrict__ Wcx, const float* __restrict__ bcx,
    const float* __restrict__ Wch, const float* __restrict__ bch,
    const float* __restrict__ Wox, const float* __restrict__ boxb,
    const float* __restrict__ Woh, const float* __restrict__ boh,
    const float* __restrict__ gw1, const float* __restrict__ gw2,
    float* __restrict__ dout)
{
    extern __shared__ float sm[];
    float* sX = sm;
    float* sC = sX + NBHP;
    float* sH = sC + 2 * NBHP;
    float* tC = sH + 4 * NBHP;
    float* tH = tC + NBHP;

    const int tid = threadIdx.x;
    const int w   = tid >> 5;      // warp id 0..7 -> row residue
    const int n   = tid & 31;      // lane = sample within tile
    const int b0  = blockIdx.x * NB;
    const int MROWS = (w < 4) ? 20 : 19;   // rows r = w + 8*m, r < 156

    // zero c and h states (sC..sH contiguous: 6*NBHP)
    for (int i = tid; i < 6 * NBHP; i += TPB) sC[i] = 0.0f;
    __syncthreads();

    for (int t = 0; t < TT; ++t) {
        // ---- load x_t tile transposed [n][h] ----
        for (int i = tid; i < NB * H; i += TPB) {
            int nn = i / H, hh = i - nn * H;
            sX[nn * HP + hh] = x[((size_t)(b0 + nn) * TT + t) * H + hh];
        }
        __syncthreads();

        const int p = t & 1;
        for (int j = 0; j < 2; ++j) {
            float* cbuf = sC + j * NBHP;
            float* hR   = sH + (j * 2 + p) * NBHP;        // read (post-GCN) hidden
            float* hW   = sH + (j * 2 + (1 - p)) * NBHP;  // write ht here

            if (t > 0) {
                const float w1 = gw1[j], w2 = gw2[j];
                // ---- GCN phase A: tmp = relu(w1 * adj @ state), both states ----
                for (int m = 0; m < MROWS; ++m) {
                    const int r = w + 8 * m;
                    const float4* ar = (const float4*)(adj + r * H);
                    const float4* cc = (const float4*)(cbuf + n * HP);
                    const float4* hh4 = (const float4*)(hR + n * HP);
                    float ac = 0.0f, ah = 0.0f;
                    #pragma unroll 13
                    for (int kk = 0; kk < H / 4; ++kk) {
                        float4 a4 = ar[kk];
                        float4 c4 = cc[kk];
                        float4 h4 = hh4[kk];
                        ac += a4.x * c4.x; ah += a4.x * h4.x;
                        ac += a4.y * c4.y; ah += a4.y * h4.y;
                        ac += a4.z * c4.z; ah += a4.z * h4.z;
                        ac += a4.w * c4.w; ah += a4.w * h4.w;
                    }
                    tC[n * HP + r] = fmaxf(w1 * ac, 0.0f);
                    tH[n * HP + r] = fmaxf(w1 * ah, 0.0f);
                }
                __syncthreads();
                // ---- GCN phase B: state = sigmoid(w2 * adj @ tmp), in place ----
                for (int m = 0; m < MROWS; ++m) {
                    const int r = w + 8 * m;
                    const float4* ar = (const float4*)(adj + r * H);
                    const float4* cc = (const float4*)(tC + n * HP);
                    const float4* hh4 = (const float4*)(tH + n * HP);
                    float ac = 0.0f, ah = 0.0f;
                    #pragma unroll 13
                    for (int kk = 0; kk < H / 4; ++kk) {
                        float4 a4 = ar[kk];
                        float4 c4 = cc[kk];
                        float4 h4 = hh4[kk];
                        ac += a4.x * c4.x; ah += a4.x * h4.x;
                        ac += a4.y * c4.y; ah += a4.y * h4.y;
                        ac += a4.z * c4.z; ah += a4.z * h4.z;
                        ac += a4.w * c4.w; ah += a4.w * h4.w;
                    }
                    cbuf[n * HP + r] = sigm(w2 * ac);
                    hR[n * HP + r]   = sigm(w2 * ah);
                }
                __syncthreads();
            }

            // ---- gate phase ----
            for (int m = 0; m < MROWS; ++m) {
                const int r = w + 8 * m;
                const int jr = j * H + r;
                const int roff = jr * H;
                const float4* wix4 = (const float4*)(Wix + roff);
                const float4* wih4 = (const float4*)(Wih + roff);
                const float4* wfx4 = (const float4*)(Wfx + roff);
                const float4* wfh4 = (const float4*)(Wfh + roff);
                const float4* wcx4 = (const float4*)(Wcx + roff);
                const float4* wch4 = (const float4*)(Wch + roff);
                const float4* wox4 = (const float4*)(Wox + roff);
                const float4* woh4 = (const float4*)(Woh + roff);
                const float4* xv4 = (const float4*)(sX + n * HP);
                const float4* hv4 = (const float4*)(hR + n * HP);

                float ai = bix[jr] + bih[jr];
                float af = bfx[jr] + bfh[jr];
                float ag = bcx[jr] + bch[jr];
                float ao = boxb[jr] + boh[jr];

                #pragma unroll 13
                for (int kk = 0; kk < H / 4; ++kk) {
                    float4 xv = xv4[kk];
                    float4 hv = hv4[kk];
                    float4 qix = wix4[kk];
                    float4 qih = wih4[kk];
                    float4 qfx = wfx4[kk];
                    float4 qfh = wfh4[kk];
                    float4 qcx = wcx4[kk];
                    float4 qch = wch4[kk];
                    float4 qox = wox4[kk];
                    float4 qoh = woh4[kk];
                    ai += qix.x * xv.x; af += qfx.x * xv.x; ag += qcx.x * xv.x; ao += qox.x * xv.x;
                    ai += qix.y * xv.y; af += qfx.y * xv.y; ag += qcx.y * xv.y; ao += qox.y * xv.y;
                    ai += qix.z * xv.z; af += qfx.z * xv.z; ag += qcx.z * xv.z; ao += qox.z * xv.z;
                    ai += qix.w * xv.w; af += qfx.w * xv.w; ag += qcx.w * xv.w; ao += qox.w * xv.w;
                    ai += qih.x * hv.x; af += qfh.x * hv.x; ag += qch.x * hv.x; ao += qoh.x * hv.x;
                    ai += qih.y * hv.y; af += qfh.y * hv.y; ag += qch.y * hv.y; ao += qoh.y * hv.y;
                    ai += qih.z * hv.z; af += qfh.z * hv.z; ag += qch.z * hv.z; ao += qoh.z * hv.z;
                    ai += qih.w * hv.w; af += qfh.w * hv.w; ag += qch.w * hv.w; ao += qoh.w * hv.w;
                }

                const float it = sigm(ai);
                const float ft = sigm(af);
                const float ot = sigm(ao);
                const float cand = tanhf(ag);
                const float cprev = cbuf[n * HP + r];
                const float ct = ft * cprev + it * cand;
                const float ht = ot * tanhf(ct);
                cbuf[n * HP + r] = ct;
                hW[n * HP + r]   = ht;
            }
            __syncthreads();
        }

        // ---- dump layer-1 ht (in sH[1][1-p]) to ys scratch, coalesced ----
        const float* h1 = sH + (1 * 2 + (1 - p)) * NBHP;
        for (int i = tid; i < NB * H; i += TPB) {
            int nn = i / H, hh = i - nn * H;
            g_ys[((size_t)(b0 + nn) * TT + t) * H + hh] = h1[nn * HP + hh];
        }
        __syncthreads();
    }

    // ---- final h_n / c_n (final h is in parity buffer 0: 1-(127&1)) ----
    for (int i = tid; i < 2 * NB * H; i += TPB) {
        int j = i / (NB * H);
        int rem = i - j * NB * H;
        int nn = rem / H, hh = rem - nn * H;
        size_t gi = ((size_t)j * BSZ + b0 + nn) * H + hh;
        dout[OFF_H + gi] = sH[(j * 2 + 0) * NBHP + nn * HP + hh];
        dout[OFF_C + gi] = sC[j * NBHP + nn * HP + hh];
    }
}

// ---------------------------------------------------------------------------
// Kernel 2: output projection. Per sample b:
//   buf[19968] (= ys flat, t*156+h) reinterpreted [156][128];
//   out[b][f*12+o] = b_out[o] + sum_t2 buf[f*128+t2] * W_out[o][t2]
// The final torch .view just linearly reinterprets -> write flat idx = f*12+o.
// ---------------------------------------------------------------------------
__global__ void __launch_bounds__(TPB) proj_kernel(
    const float* __restrict__ Wout, const float* __restrict__ bout,
    float* __restrict__ dout)
{
    extern __shared__ float pm[];
    float* sWt  = pm;                 // transposed: [t2][12]
    float* sBuf = pm + TT * OUT_O;    // 19968 floats

    const int b = blockIdx.x;
    const int tid = threadIdx.x;

    for (int i = tid; i < OUT_O * TT; i += TPB) {
        int o = i / TT, t2 = i - o * TT;
        sWt[t2 * OUT_O + o] = Wout[i];
    }
    const float* src = g_ys + (size_t)b * (TT * H);
    for (int i = tid; i < TT * H; i += TPB) sBuf[i] = src[i];
    __syncthreads();

    for (int idx = tid; idx < H * OUT_O; idx += TPB) {
        int f = idx / OUT_O, o = idx - f * OUT_O;
        float acc = bout[o];
        const float* bf = sBuf + f * TT;
        #pragma unroll 8
        for (int t2 = 0; t2 < TT; ++t2)
            acc += bf[t2] * sWt[t2 * OUT_O + o];
        dout[(size_t)b * (H * OUT_O) + idx] = acc;
    }
}

// ---------------------------------------------------------------------------
extern "C" void kernel_launch(void* const* d_in, const int* in_sizes, int n_in,
                              void* d_out, int out_size)
{
    const float* x    = (const float*)d_in[0];
    const float* adj  = (const float*)d_in[1];
    const float* Wix  = (const float*)d_in[2];
    const float* bix  = (const float*)d_in[3];
    const float* Wih  = (const float*)d_in[4];
    const float* bih  = (const float*)d_in[5];
    const float* Wfx  = (const float*)d_in[6];
    const float* bfx  = (const float*)d_in[7];
    const float* Wfh  = (const float*)d_in[8];
    const float* bfh  = (const float*)d_in[9];
    const float* Wcx  = (const float*)d_in[10];
    const float* bcx  = (const float*)d_in[11];
    const float* Wch  = (const float*)d_in[12];
    const float* bch  = (const float*)d_in[13];
    const float* Wox  = (const float*)d_in[14];
    const float* boxb = (const float*)d_in[15];
    const float* Woh  = (const float*)d_in[16];
    const float* boh  = (const float*)d_in[17];
    const float* gw1  = (const float*)d_in[18];
    const float* gw2  = (const float*)d_in[19];
    const float* Wout = (const float*)d_in[20];
    const float* bout = (const float*)d_in[21];
    float* out = (float*)d_out;

    const int smem1 = 9 * NBHP * (int)sizeof(float);                 // 188,928 B
    const int smem2 = (TT * OUT_O + TT * H) * (int)sizeof(float);    //  86,016 B
    cudaFuncSetAttribute(lstm_gcn_kernel,
                         cudaFuncAttributeMaxDynamicSharedMemorySize, smem1);
    cudaFuncSetAttribute(proj_kernel,
                         cudaFuncAttributeMaxDynamicSharedMemorySize, smem2);

    lstm_gcn_kernel<<<BSZ / NB, TPB, smem1>>>(
        x, adj, Wix, bix, Wih, bih, Wfx, bfx, Wfh, bfh,
        Wcx, bcx, Wch, bch, Wox, boxb, Woh, boh, gw1, gw2, out);

    proj_kernel<<<BSZ, TPB, smem2>>>(Wout, bout, out);
}

// round 10
// speedup vs baseline: 1.0450x; 1.0450x over previous
#include <cuda_runtime.h>

// ---------------------------------------------------------------------------
// Problem constants
// ---------------------------------------------------------------------------
#define H    156
#define HP   164           // padded row: 164 % 32 == 4 -> conflict-free LDS.128
#define BSZ  4096
#define TT   128
#define NB   32            // samples per block
#define TPB  512           // 16 warps: 4 per SMSP for latency hiding
#define NWARP 16
#define NBHP (NB * HP)     // 5248 floats
#define OUT_O 12

#define OUT_SZ  ((size_t)BSZ * H * OUT_O)        // 7,667,712
#define OFF_H   (OUT_SZ)
#define OFF_C   (OFF_H + 2ULL * BSZ * H)

// scratch for layer-1 ht time series: [B][T][H]  (t*156+h flat per sample)
__device__ float g_ys[(size_t)BSZ * TT * H];

__device__ __forceinline__ float sigm(float x) {
    return __fdividef(1.0f, 1.0f + __expf(-x));
}

// packed f32x2 FMA: d.lo += a.lo*b.lo ; d.hi += a.hi*b.hi  (sm_100+ PTX only)
__device__ __forceinline__ void ffma2(unsigned long long& d,
                                      const unsigned long long a,
                                      const unsigned long long b) {
    asm("fma.rn.f32x2 %0, %1, %2, %0;" : "+l"(d) : "l"(a), "l"(b));
}
__device__ __forceinline__ float hsum2(unsigned long long v) {
    float lo, hi;
    asm("mov.b64 {%0,%1}, %2;" : "=f"(lo), "=f"(hi) : "l"(v));
    return lo + hi;
}

// ---------------------------------------------------------------------------
// Kernel 1: persistent LSTM+GCN recurrence. 128 blocks x 512 threads.
// SMEM layout (floats):
//   sX  [NBHP]        x_t transposed [n][HP]
//   sC  [2*NBHP]      cell state per layer, [n][HP]
//   sH  [2*2*NBHP]    hidden state per layer, ping-pong by t-parity
//   tC  [NBHP]        GCN relu intermediate (c)
//   tH  [NBHP]        GCN relu intermediate (h)
// total = 9*NBHP floats = 188,928 bytes
// ---------------------------------------------------------------------------
__global__ void __launch_bounds__(TPB, 1) lstm_gcn_kernel(
    const float* __restrict__ x,   const float* __restrict__ adj,
    const float* __restrict__ Wix, const float* __restrict__ bix,
    const float* __restrict__ Wih, const float* __restrict__ bih,
    const float* __restrict__ Wfx, const float* __restrict__ bfx,
    const float* __restrict__ Wfh, const float* __restrict__ bfh,
    const float* __restrict__ Wcx, const float* __restrict__ bcx,
    const float* __restrict__ Wch, const float* __restrict__ bch,
    const float* __restrict__ Wox, const float* __restrict__ boxb,
    const float* __restrict__ Woh, const float* __restrict__ boh,
    const float* __restrict__ gw1, const float* __restrict__ gw2,
    float* __restrict__ dout)
{
    extern __shared__ float sm[];
    float* sX = sm;
    float* sC = sX + NBHP;
    float* sH = sC + 2 * NBHP;
    float* tC = sH + 4 * NBHP;
    float* tH = tC + NBHP;

    const int tid = threadIdx.x;
    const int w   = tid >> 5;      // warp id 0..15 -> row residue
    const int n   = tid & 31;      // lane = sample within tile
    const int b0  = blockIdx.x * NB;
    const int MROWS = (w < 12) ? 10 : 9;   // rows r = w + 16*m, r < 156

    // zero c and h states (sC..sH contiguous: 6*NBHP)
    for (int i = tid; i < 6 * NBHP; i += TPB) sC[i] = 0.0f;
    __syncthreads();

    for (int t = 0; t < TT; ++t) {
        // ---- load x_t tile transposed [n][h] ----
        for (int i = tid; i < NB * H; i += TPB) {
            int nn = i / H, hh = i - nn * H;
            sX[nn * HP + hh] = x[((size_t)(b0 + nn) * TT + t) * H + hh];
        }
        __syncthreads();

        const int p = t & 1;
        for (int j = 0; j < 2; ++j) {
            float* cbuf = sC + j * NBHP;
            float* hR   = sH + (j * 2 + p) * NBHP;        // read (post-GCN) hidden
            float* hW   = sH + (j * 2 + (1 - p)) * NBHP;  // write ht here

            if (t > 0) {
                const float w1 = gw1[j], w2 = gw2[j];
                // ---- GCN phase A: tmp = relu(w1 * adj @ state), both states ----
                for (int m = 0; m < MROWS; ++m) {
                    const int r = w + 16 * m;
                    const ulonglong2* ar  = (const ulonglong2*)(adj + r * H);
                    const ulonglong2* cc  = (const ulonglong2*)(cbuf + n * HP);
                    const ulonglong2* hh2 = (const ulonglong2*)(hR + n * HP);
                    unsigned long long ac0 = 0, ac1 = 0, ah0 = 0, ah1 = 0;
                    #pragma unroll 13
                    for (int kk = 0; kk < H / 4; ++kk) {
                        ulonglong2 a4 = ar[kk];
                        ulonglong2 c4 = cc[kk];
                        ulonglong2 h4 = hh2[kk];
                        ffma2(ac0, a4.x, c4.x);
                        ffma2(ah0, a4.x, h4.x);
                        ffma2(ac1, a4.y, c4.y);
                        ffma2(ah1, a4.y, h4.y);
                    }
                    float ac = hsum2(ac0) + hsum2(ac1);
                    float ah = hsum2(ah0) + hsum2(ah1);
                    tC[n * HP + r] = fmaxf(w1 * ac, 0.0f);
                    tH[n * HP + r] = fmaxf(w1 * ah, 0.0f);
                }
                __syncthreads();
                // ---- GCN phase B: state = sigmoid(w2 * adj @ tmp), in place ----
                for (int m = 0; m < MROWS; ++m) {
                    const int r = w + 16 * m;
                    const ulonglong2* ar  = (const ulonglong2*)(adj + r * H);
                    const ulonglong2* cc  = (const ulonglong2*)(tC + n * HP);
                    const ulonglong2* hh2 = (const ulonglong2*)(tH + n * HP);
                    unsigned long long ac0 = 0, ac1 = 0, ah0 = 0, ah1 = 0;
                    #pragma unroll 13
                    for (int kk = 0; kk < H / 4; ++kk) {
                        ulonglong2 a4 = ar[kk];
                        ulonglong2 c4 = cc[kk];
                        ulonglong2 h4 = hh2[kk];
                        ffma2(ac0, a4.x, c4.x);
                        ffma2(ah0, a4.x, h4.x);
                        ffma2(ac1, a4.y, c4.y);
                        ffma2(ah1, a4.y, h4.y);
                    }
                    float ac = hsum2(ac0) + hsum2(ac1);
                    float ah = hsum2(ah0) + hsum2(ah1);
                    cbuf[n * HP + r] = sigm(w2 * ac);
                    hR[n * HP + r]   = sigm(w2 * ah);
                }
                __syncthreads();
            }

            // ---- gate phase ----
            for (int m = 0; m < MROWS; ++m) {
                const int r = w + 16 * m;
                const int jr = j * H + r;
                const int roff = jr * H;
                const ulonglong2* wix2 = (const ulonglong2*)(Wix + roff);
                const ulonglong2* wih2 = (const ulonglong2*)(Wih + roff);
                const ulonglong2* wfx2 = (const ulonglong2*)(Wfx + roff);
                const ulonglong2* wfh2 = (const ulonglong2*)(Wfh + roff);
                const ulonglong2* wcx2 = (const ulonglong2*)(Wcx + roff);
                const ulonglong2* wch2 = (const ulonglong2*)(Wch + roff);
                const ulonglong2* wox2 = (const ulonglong2*)(Wox + roff);
                const ulonglong2* woh2 = (const ulonglong2*)(Woh + roff);
                const ulonglong2* xv2  = (const ulonglong2*)(sX + n * HP);
                const ulonglong2* hv2  = (const ulonglong2*)(hR + n * HP);

                unsigned long long ai2 = 0, af2 = 0, ag2 = 0, ao2 = 0;

                #pragma unroll 13
                for (int kk = 0; kk < H / 4; ++kk) {
                    ulonglong2 xv = xv2[kk];
                    ulonglong2 hv = hv2[kk];
                    ulonglong2 qix = wix2[kk];
                    ulonglong2 qih = wih2[kk];
                    ulonglong2 qfx = wfx2[kk];
                    ulonglong2 qfh = wfh2[kk];
                    ulonglong2 qcx = wcx2[kk];
                    ulonglong2 qch = wch2[kk];
                    ulonglong2 qox = wox2[kk];
                    ulonglong2 qoh = woh2[kk];
                    ffma2(ai2, qix.x, xv.x); ffma2(af2, qfx.x, xv.x);
                    ffma2(ag2, qcx.x, xv.x); ffma2(ao2, qox.x, xv.x);
                    ffma2(ai2, qix.y, xv.y); ffma2(af2, qfx.y, xv.y);
                    ffma2(ag2, qcx.y, xv.y); ffma2(ao2, qox.y, xv.y);
                    ffma2(ai2, qih.x, hv.x); ffma2(af2, qfh.x, hv.x);
                    ffma2(ag2, qch.x, hv.x); ffma2(ao2, qoh.x, hv.x);
                    ffma2(ai2, qih.y, hv.y); ffma2(af2, qfh.y, hv.y);
                    ffma2(ag2, qch.y, hv.y); ffma2(ao2, qoh.y, hv.y);
                }

                const float ai = bix[jr] + bih[jr] + hsum2(ai2);
                const float af = bfx[jr] + bfh[jr] + hsum2(af2);
                const float ag = bcx[jr] + bch[jr] + hsum2(ag2);
                const float ao = boxb[jr] + boh[jr] + hsum2(ao2);

                const float it = sigm(ai);
                const float ft = sigm(af);
                const float ot = sigm(ao);
                const float cand = tanhf(ag);
                const float cprev = cbuf[n * HP + r];
                const float ct = ft * cprev + it * cand;
                const float ht = ot * tanhf(ct);
                cbuf[n * HP + r] = ct;
                hW[n * HP + r]   = ht;
            }
            __syncthreads();
        }

        // ---- dump layer-1 ht (in sH[1][1-p]) to ys scratch, coalesced ----
        const float* h1 = sH + (1 * 2 + (1 - p)) * NBHP;
        for (int i = tid; i < NB * H; i += TPB) {
            int nn = i / H, hh = i - nn * H;
            g_ys[((size_t)(b0 + nn) * TT + t) * H + hh] = h1[nn * HP + hh];
        }
        __syncthreads();
    }

    // ---- final h_n / c_n (final h is in parity buffer 0 after t=127) ----
    for (int i = tid; i < 2 * NB * H; i += TPB) {
        int j = i / (NB * H);
        int rem = i - j * NB * H;
        int nn = rem / H, hh = rem - nn * H;
        size_t gi = ((size_t)j * BSZ + b0 + nn) * H + hh;
        dout[OFF_H + gi] = sH[(j * 2 + 0) * NBHP + nn * HP + hh];
        dout[OFF_C + gi] = sC[j * NBHP + nn * HP + hh];
    }
}

// ---------------------------------------------------------------------------
// Kernel 2: output projection. Per sample b:
//   buf[19968] (= ys flat, t*156+h) reinterpreted [156][128];
//   out[b][f*12+o] = b_out[o] + sum_t2 buf[f*128+t2] * W_out[o][t2]
// ---------------------------------------------------------------------------
__global__ void __launch_bounds__(256) proj_kernel(
    const float* __restrict__ Wout, const float* __restrict__ bout,
    float* __restrict__ dout)
{
    extern __shared__ float pm[];
    float* sWt  = pm;                 // transposed: [t2][12]
    float* sBuf = pm + TT * OUT_O;    // 19968 floats

    const int b = blockIdx.x;
    const int tid = threadIdx.x;

    for (int i = tid; i < OUT_O * TT; i += 256) {
        int o = i / TT, t2 = i - o * TT;
        sWt[t2 * OUT_O + o] = Wout[i];
    }
    const float* src = g_ys + (size_t)b * (TT * H);
    for (int i = tid; i < TT * H; i += 256) sBuf[i] = src[i];
    __syncthreads();

    for (int idx = tid; idx < H * OUT_O; idx += 256) {
        int f = idx / OUT_O, o = idx - f * OUT_O;
        float acc = bout[o];
        const float* bf = sBuf + f * TT;
        #pragma unroll 8
        for (int t2 = 0; t2 < TT; ++t2)
            acc += bf[t2] * sWt[t2 * OUT_O + o];
        dout[(size_t)b * (H * OUT_O) + idx] = acc;
    }
}

// ---------------------------------------------------------------------------
extern "C" void kernel_launch(void* const* d_in, const int* in_sizes, int n_in,
                              void* d_out, int out_size)
{
    const float* x    = (const float*)d_in[0];
    const float* adj  = (const float*)d_in[1];
    const float* Wix  = (const float*)d_in[2];
    const float* bix  = (const float*)d_in[3];
    const float* Wih  = (const float*)d_in[4];
    const float* bih  = (const float*)d_in[5];
    const float* Wfx  = (const float*)d_in[6];
    const float* bfx  = (const float*)d_in[7];
    const float* Wfh  = (const float*)d_in[8];
    const float* bfh  = (const float*)d_in[9];
    const float* Wcx  = (const float*)d_in[10];
    const float* bcx  = (const float*)d_in[11];
    const float* Wch  = (const float*)d_in[12];
    const float* bch  = (const float*)d_in[13];
    const float* Wox  = (const float*)d_in[14];
    const float* boxb = (const float*)d_in[15];
    const float* Woh  = (const float*)d_in[16];
    const float* boh  = (const float*)d_in[17];
    const float* gw1  = (const float*)d_in[18];
    const float* gw2  = (const float*)d_in[19];
    const float* Wout = (const float*)d_in[20];
    const float* bout = (const float*)d_in[21];
    float* out = (float*)d_out;

    const int smem1 = 9 * NBHP * (int)sizeof(float);                 // 188,928 B
    const int smem2 = (TT * OUT_O + TT * H) * (int)sizeof(float);    //  86,016 B
    cudaFuncSetAttribute(lstm_gcn_kernel,
                         cudaFuncAttributeMaxDynamicSharedMemorySize, smem1);
    cudaFuncSetAttribute(proj_kernel,
                         cudaFuncAttributeMaxDynamicSharedMemorySize, smem2);

    lstm_gcn_kernel<<<BSZ / NB, TPB, smem1>>>(
        x, adj, Wix, bix, Wih, bih, Wfx, bfx, Wfh, bfh,
        Wcx, bcx, Wch, bch, Wox, boxb, Woh, boh, gw1, gw2, out);

    proj_kernel<<<BSZ, 256, smem2>>>(Wout, bout, out);
}

// round 11
// speedup vs baseline: 1.2343x; 1.1811x over previous
#include <cuda_runtime.h>

// ---------------------------------------------------------------------------
// Problem constants
// ---------------------------------------------------------------------------
#define H    156
#define HP   164           // padded row: 164 % 32 == 4 -> conflict-free LDS.128
#define BSZ  4096
#define TT   128
#define NB   32            // samples per block
#define TPB  256           // 8 warps; 255-reg budget for 16-stream gate loop
#define NBHP (NB * HP)     // 5248 floats
#define OUT_O 12

#define OUT_SZ  ((size_t)BSZ * H * OUT_O)        // 7,667,712
#define OFF_H   (OUT_SZ)
#define OFF_C   (OFF_H + 2ULL * BSZ * H)

typedef unsigned long long u64;

// scratch for layer-1 ht time series: [B][T][H]  (t*156+h flat per sample)
__device__ float g_ys[(size_t)BSZ * TT * H];

__device__ __forceinline__ float sigm(float x) {
    return __fdividef(1.0f, 1.0f + __expf(-x));
}

// packed f32x2 FMA: d.lo += a.lo*b.lo ; d.hi += a.hi*b.hi  (sm_100+ PTX only)
__device__ __forceinline__ void ffma2(u64& d, const u64 a, const u64 b) {
    asm("fma.rn.f32x2 %0, %1, %2, %0;" : "+l"(d) : "l"(a), "l"(b));
}
__device__ __forceinline__ float hsum2(u64 v) {
    float lo, hi;
    asm("mov.b64 {%0,%1}, %2;" : "=f"(lo), "=f"(hi) : "l"(v));
    return lo + hi;
}

// ---------------------------------------------------------------------------
// Fused kernel: persistent LSTM+GCN recurrence + output projection epilogue.
// 128 blocks x 256 threads. Row-pair blocking: warp w owns row pairs
// q = w + 8*m (q < 78), rows r0=2q, r1=2q+1 -> each state chunk loaded from
// SMEM feeds BOTH rows' accumulators (halves crossbar traffic).
//
// SMEM layout (floats):
//   sX  [NBHP]        x_t transposed [n][HP]
//   sC  [2*NBHP]      cell state per layer, [n][HP]
//   sH  [2*2*NBHP]    hidden state per layer, ping-pong by t-parity
//   tC  [NBHP]        GCN relu intermediate (c)
//   tH  [NBHP]        GCN relu intermediate (h)
// total = 9*NBHP floats = 188,928 bytes (epilogue reuses the same arena)
// ---------------------------------------------------------------------------
__global__ void __launch_bounds__(TPB, 1) lstm_gcn_fused_kernel(
    const float* __restrict__ x,   const float* __restrict__ adj,
    const float* __restrict__ Wix, const float* __restrict__ bix,
    const float* __restrict__ Wih, const float* __restrict__ bih,
    const float* __restrict__ Wfx, const float* __restrict__ bfx,
    const float* __restrict__ Wfh, const float* __restrict__ bfh,
    const float* __restrict__ Wcx, const float* __restrict__ bcx,
    const float* __restrict__ Wch, const float* __restrict__ bch,
    const float* __restrict__ Wox, const float* __restrict__ boxb,
    const float* __restrict__ Woh, const float* __restrict__ boh,
    const float* __restrict__ gw1, const float* __restrict__ gw2,
    const float* __restrict__ Wout, const float* __restrict__ bout,
    float* __restrict__ dout)
{
    extern __shared__ float sm[];
    float* sX = sm;
    float* sC = sX + NBHP;
    float* sH = sC + 2 * NBHP;
    float* tC = sH + 4 * NBHP;
    float* tH = tC + NBHP;

    const int tid = threadIdx.x;
    const int w   = tid >> 5;      // warp id 0..7
    const int n   = tid & 31;      // lane = sample within tile
    const int b0  = blockIdx.x * NB;
    // 78 row-pairs: warps 0..5 take 10, warps 6..7 take 9 (q = w + 8m < 78)
    const int QROWS = (w < 6) ? 10 : 9;

    // zero c and h states (sC..sH contiguous: 6*NBHP)
    for (int i = tid; i < 6 * NBHP; i += TPB) sC[i] = 0.0f;
    __syncthreads();

    for (int t = 0; t < TT; ++t) {
        // ---- load x_t tile transposed [n][h] ----
        for (int i = tid; i < NB * H; i += TPB) {
            int nn = i / H, hh = i - nn * H;
            sX[nn * HP + hh] = x[((size_t)(b0 + nn) * TT + t) * H + hh];
        }
        __syncthreads();

        const int p = t & 1;
        for (int j = 0; j < 2; ++j) {
            float* cbuf = sC + j * NBHP;
            float* hR   = sH + (j * 2 + p) * NBHP;        // read (post-GCN) hidden
            float* hW   = sH + (j * 2 + (1 - p)) * NBHP;  // write ht here

            if (t > 0) {
                const float g1 = gw1[j], g2 = gw2[j];
                // ---- GCN phase A: tmp = relu(g1 * adj @ state), both states,
                //      2 rows per pass share the state loads ----
                for (int m = 0; m < QROWS; ++m) {
                    const int q = w + 8 * m;
                    const int r0 = 2 * q;
                    const ulonglong2* a0  = (const ulonglong2*)(adj + r0 * H);
                    const ulonglong2* a1  = (const ulonglong2*)(adj + (r0 + 1) * H);
                    const ulonglong2* cc  = (const ulonglong2*)(cbuf + n * HP);
                    const ulonglong2* hh2 = (const ulonglong2*)(hR + n * HP);
                    u64 ac0 = 0, ac1 = 0, ah0 = 0, ah1 = 0;
                    #pragma unroll 13
                    for (int kk = 0; kk < H / 4; ++kk) {
                        ulonglong2 c4 = cc[kk];
                        ulonglong2 h4 = hh2[kk];
                        ulonglong2 w0 = a0[kk];
                        ulonglong2 w1 = a1[kk];
                        ffma2(ac0, w0.x, c4.x); ffma2(ac0, w0.y, c4.y);
                        ffma2(ah0, w0.x, h4.x); ffma2(ah0, w0.y, h4.y);
                        ffma2(ac1, w1.x, c4.x); ffma2(ac1, w1.y, c4.y);
                        ffma2(ah1, w1.x, h4.x); ffma2(ah1, w1.y, h4.y);
                    }
                    tC[n * HP + r0]     = fmaxf(g1 * hsum2(ac0), 0.0f);
                    tH[n * HP + r0]     = fmaxf(g1 * hsum2(ah0), 0.0f);
                    tC[n * HP + r0 + 1] = fmaxf(g1 * hsum2(ac1), 0.0f);
                    tH[n * HP + r0 + 1] = fmaxf(g1 * hsum2(ah1), 0.0f);
                }
                __syncthreads();
                // ---- GCN phase B: state = sigmoid(g2 * adj @ tmp) ----
                for (int m = 0; m < QROWS; ++m) {
                    const int q = w + 8 * m;
                    const int r0 = 2 * q;
                    const ulonglong2* a0  = (const ulonglong2*)(adj + r0 * H);
                    const ulonglong2* a1  = (const ulonglong2*)(adj + (r0 + 1) * H);
                    const ulonglong2* cc  = (const ulonglong2*)(tC + n * HP);
                    const ulonglong2* hh2 = (const ulonglong2*)(tH + n * HP);
                    u64 ac0 = 0, ac1 = 0, ah0 = 0, ah1 = 0;
                    #pragma unroll 13
                    for (int kk = 0; kk < H / 4; ++kk) {
                        ulonglong2 c4 = cc[kk];
                        ulonglong2 h4 = hh2[kk];
                        ulonglong2 w0 = a0[kk];
                        ulonglong2 w1 = a1[kk];
                        ffma2(ac0, w0.x, c4.x); ffma2(ac0, w0.y, c4.y);
                        ffma2(ah0, w0.x, h4.x); ffma2(ah0, w0.y, h4.y);
                        ffma2(ac1, w1.x, c4.x); ffma2(ac1, w1.y, c4.y);
                        ffma2(ah1, w1.x, h4.x); ffma2(ah1, w1.y, h4.y);
                    }
                    cbuf[n * HP + r0]     = sigm(g2 * hsum2(ac0));
                    hR[n * HP + r0]       = sigm(g2 * hsum2(ah0));
                    cbuf[n * HP + r0 + 1] = sigm(g2 * hsum2(ac1));
                    hR[n * HP + r0 + 1]   = sigm(g2 * hsum2(ah1));
                }
                __syncthreads();
            }

            // ---- gate phase: 2 rows per pass share x/h loads ----
            for (int m = 0; m < QROWS; ++m) {
                const int q = w + 8 * m;
                const int r0 = 2 * q;
                const int jr0 = j * H + r0;
                const size_t o0 = (size_t)jr0 * H;
                const size_t o1 = (size_t)(jr0 + 1) * H;

                const ulonglong2* ix0 = (const ulonglong2*)(Wix + o0);
                const ulonglong2* ih0 = (const ulonglong2*)(Wih + o0);
                const ulonglong2* fx0 = (const ulonglong2*)(Wfx + o0);
                const ulonglong2* fh0 = (const ulonglong2*)(Wfh + o0);
                const ulonglong2* cx0 = (const ulonglong2*)(Wcx + o0);
                const ulonglong2* ch0 = (const ulonglong2*)(Wch + o0);
                const ulonglong2* ox0 = (const ulonglong2*)(Wox + o0);
                const ulonglong2* oh0 = (const ulonglong2*)(Woh + o0);
                const ulonglong2* ix1 = (const ulonglong2*)(Wix + o1);
                const ulonglong2* ih1 = (const ulonglong2*)(Wih + o1);
                const ulonglong2* fx1 = (const ulonglong2*)(Wfx + o1);
                const ulonglong2* fh1 = (const ulonglong2*)(Wfh + o1);
                const ulonglong2* cx1 = (const ulonglong2*)(Wcx + o1);
                const ulonglong2* ch1 = (const ulonglong2*)(Wch + o1);
                const ulonglong2* ox1 = (const ulonglong2*)(Wox + o1);
                const ulonglong2* oh1 = (const ulonglong2*)(Woh + o1);
                const ulonglong2* xv2 = (const ulonglong2*)(sX + n * HP);
                const ulonglong2* hv2 = (const ulonglong2*)(hR + n * HP);

                u64 Ai0 = 0, Af0 = 0, Ag0 = 0, Ao0 = 0;
                u64 Ai1 = 0, Af1 = 0, Ag1 = 0, Ao1 = 0;

                #pragma unroll 13
                for (int kk = 0; kk < H / 4; ++kk) {
                    ulonglong2 xv = xv2[kk];
                    ulonglong2 hv = hv2[kk];
                    {
                        ulonglong2 qx = ix0[kk], qh = ih0[kk];
                        ffma2(Ai0, qx.x, xv.x); ffma2(Ai0, qx.y, xv.y);
                        ffma2(Ai0, qh.x, hv.x); ffma2(Ai0, qh.y, hv.y);
                    }
                    {
                        ulonglong2 qx = fx0[kk], qh = fh0[kk];
                        ffma2(Af0, qx.x, xv.x); ffma2(Af0, qx.y, xv.y);
                        ffma2(Af0, qh.x, hv.x); ffma2(Af0, qh.y, hv.y);
                    }
                    {
                        ulonglong2 qx = cx0[kk], qh = ch0[kk];
                        ffma2(Ag0, qx.x, xv.x); ffma2(Ag0, qx.y, xv.y);
                        ffma2(Ag0, qh.x, hv.x); ffma2(Ag0, qh.y, hv.y);
                    }
                    {
                        ulonglong2 qx = ox0[kk], qh = oh0[kk];
                        ffma2(Ao0, qx.x, xv.x); ffma2(Ao0, qx.y, xv.y);
                        ffma2(Ao0, qh.x, hv.x); ffma2(Ao0, qh.y, hv.y);
                    }
                    {
                        ulonglong2 qx = ix1[kk], qh = ih1[kk];
                        ffma2(Ai1, qx.x, xv.x); ffma2(Ai1, qx.y, xv.y);
                        ffma2(Ai1, qh.x, hv.x); ffma2(Ai1, qh.y, hv.y);
                    }
                    {
                        ulonglong2 qx = fx1[kk], qh = fh1[kk];
                        ffma2(Af1, qx.x, xv.x); ffma2(Af1, qx.y, xv.y);
                        ffma2(Af1, qh.x, hv.x); ffma2(Af1, qh.y, hv.y);
                    }
                    {
                        ulonglong2 qx = cx1[kk], qh = ch1[kk];
                        ffma2(Ag1, qx.x, xv.x); ffma2(Ag1, qx.y, xv.y);
                        ffma2(Ag1, qh.x, hv.x); ffma2(Ag1, qh.y, hv.y);
                    }
                    {
                        ulonglong2 qx = ox1[kk], qh = oh1[kk];
                        ffma2(Ao1, qx.x, xv.x); ffma2(Ao1, qx.y, xv.y);
                        ffma2(Ao1, qh.x, hv.x); ffma2(Ao1, qh.y, hv.y);
                    }
                }

                // LSTM cell epilogue for both rows
                auto emit = [&](int r, int jr, u64 Ai, u64 Af, u64 Ag, u64 Ao) {
                    const float ai = bix[jr] + bih[jr] + hsum2(Ai);
                    const float af = bfx[jr] + bfh[jr] + hsum2(Af);
                    const float ag = bcx[jr] + bch[jr] + hsum2(Ag);
                    const float ao = boxb[jr] + boh[jr] + hsum2(Ao);
                    const float it = sigm(ai);
                    const float ft = sigm(af);
                    const float ot = sigm(ao);
                    const float cand = tanhf(ag);
                    const float cp = cbuf[n * HP + r];
                    const float ct = ft * cp + it * cand;
                    const float ht = ot * tanhf(ct);
                    cbuf[n * HP + r] = ct;
                    hW[n * HP + r]   = ht;
                };
                emit(r0,     jr0,     Ai0, Af0, Ag0, Ao0);
                emit(r0 + 1, jr0 + 1, Ai1, Af1, Ag1, Ao1);
            }
            __syncthreads();
        }

        // ---- dump layer-1 ht (in sH[1][1-p]) to ys scratch, coalesced ----
        const float* h1 = sH + (1 * 2 + (1 - p)) * NBHP;
        for (int i = tid; i < NB * H; i += TPB) {
            int nn = i / H, hh = i - nn * H;
            g_ys[((size_t)(b0 + nn) * TT + t) * H + hh] = h1[nn * HP + hh];
        }
        __syncthreads();
    }

    // ---- final h_n / c_n (final h is in parity buffer 0 after t=127) ----
    for (int i = tid; i < 2 * NB * H; i += TPB) {
        int j = i / (NB * H);
        int rem = i - j * NB * H;
        int nn = rem / H, hh = rem - nn * H;
        size_t gi = ((size_t)j * BSZ + b0 + nn) * H + hh;
        dout[OFF_H + gi] = sH[(j * 2 + 0) * NBHP + nn * HP + hh];
        dout[OFF_C + gi] = sC[j * NBHP + nn * HP + hh];
    }
    __syncthreads();

    // ---- projection epilogue (reuses SMEM arena; states are dead now) ----
    // Per sample s of this block's 32:
    //   buf[19968] = ys flat (t*156+h), viewed [156][128];
    //   out[b][f*12+o] = b_out[o] + sum_t2 buf[f*128+t2] * W_out[o][t2]
    float* sWt  = sm;                 // transposed: [t2][12]
    float* sBuf = sm + TT * OUT_O;    // 19968 floats

    for (int i = tid; i < OUT_O * TT; i += TPB) {
        int o = i / TT, t2 = i - o * TT;
        sWt[t2 * OUT_O + o] = Wout[i];
    }
    for (int s = 0; s < NB; ++s) {
        __syncthreads();   // protect sBuf overwrite vs previous reads (and sWt 1st pass)
        const float4* src4 = (const float4*)(g_ys + (size_t)(b0 + s) * (TT * H));
        for (int i = tid; i < (TT * H) / 4; i += TPB)
            ((float4*)sBuf)[i] = src4[i];
        __syncthreads();
        for (int idx = tid; idx < H * OUT_O; idx += TPB) {
            int f = idx / OUT_O, o = idx - f * OUT_O;
            float acc = bout[o];
            const float* bf = sBuf + f * TT;
            #pragma unroll 8
            for (int t2 = 0; t2 < TT; ++t2)
                acc += bf[t2] * sWt[t2 * OUT_O + o];
            dout[(size_t)(b0 + s) * (H * OUT_O) + idx] = acc;
        }
    }
}

// ---------------------------------------------------------------------------
extern "C" void kernel_launch(void* const* d_in, const int* in_sizes, int n_in,
                              void* d_out, int out_size)
{
    const float* x    = (const float*)d_in[0];
    const float* adj  = (const float*)d_in[1];
    const float* Wix  = (const float*)d_in[2];
    const float* bix  = (const float*)d_in[3];
    const float* Wih  = (const float*)d_in[4];
    const float* bih  = (const float*)d_in[5];
    const float* Wfx  = (const float*)d_in[6];
    const float* bfx  = (const float*)d_in[7];
    const float* Wfh  = (const float*)d_in[8];
    const float* bfh  = (const float*)d_in[9];
    const float* Wcx  = (const float*)d_in[10];
    const float* bcx  = (const float*)d_in[11];
    const float* Wch  = (const float*)d_in[12];
    const float* bch  = (const float*)d_in[13];
    const float* Wox  = (const float*)d_in[14];
    const float* boxb = (const float*)d_in[15];
    const float* Woh  = (const float*)d_in[16];
    const float* boh  = (const float*)d_in[17];
    const float* gw1  = (const float*)d_in[18];
    const float* gw2  = (const float*)d_in[19];
    const float* Wout = (const float*)d_in[20];
    const float* bout = (const float*)d_in[21];
    float* out = (float*)d_out;

    const int smem1 = 9 * NBHP * (int)sizeof(float);   // 188,928 B
    cudaFuncSetAttribute(lstm_gcn_fused_kernel,
                         cudaFuncAttributeMaxDynamicSharedMemorySize, smem1);

    lstm_gcn_fused_kernel<<<BSZ / NB, TPB, smem1>>>(
        x, adj, Wix, bix, Wih, bih, Wfx, bfx, Wfh, bfh,
        Wcx, bcx, Wch, bch, Wox, boxb, Woh, boh, gw1, gw2,
        Wout, bout, out);
}